// round 3
// baseline (speedup 1.0000x reference)
#include <cuda_runtime.h>
#include <cuda_bf16.h>
#include <cstdint>

typedef unsigned long long u64;

// Problem constants
#define B 4
#define C 4
#define H 256
#define W 256
#define HW (H*W)          // 65536
#define FS 11
#define PAD 5

// Tile config for attention kernel
#define BW 32             // tile width (output pixels)
#define BH 16             // tile height
#define R  4              // pixels per thread along w
#define NPIX 128          // pixel-slots per block = (BW/R)*BH
#define NTHREADS 256      // 2 ki-groups x 128 pixel-slots
#define HALO_W (BW + FS - 1)   // 42
#define HALO_H (BH + FS - 1)   // 26
#define SST 43            // shared row stride in 16B units (bank-skewed)

// Scratch: theta (pre-scaled by log2(e)), phi, g in pixel-major float4 layout.
__device__ float4 d_theta[B*HW];
__device__ float4 d_phi[B*HW];
__device__ float4 d_g[B*HW];

__device__ __forceinline__ float ex2(float s) {
    float r;
    asm("ex2.approx.f32 %0, %1;" : "=f"(r) : "f"(s));
    return r;
}
__device__ __forceinline__ u64 fma2(u64 a, u64 b, u64 c) {
    u64 d;
    asm("fma.rn.f32x2 %0, %1, %2, %3;" : "=l"(d) : "l"(a), "l"(b), "l"(c));
    return d;
}
__device__ __forceinline__ u64 add2(u64 a, u64 b) {
    u64 d;
    asm("add.rn.f32x2 %0, %1, %2;" : "=l"(d) : "l"(a), "l"(b));
    return d;
}
__device__ __forceinline__ u64 mul2(u64 a, u64 b) {
    u64 d;
    asm("mul.rn.f32x2 %0, %1, %2;" : "=l"(d) : "l"(a), "l"(b));
    return d;
}
__device__ __forceinline__ u64 dup2(float e) {
    u64 d;
    asm("mov.b64 %0, {%1, %1};" : "=l"(d) : "f"(e));
    return d;
}
__device__ __forceinline__ float2 unpack2(u64 v) {
    float2 f;
    asm("mov.b64 {%0, %1}, %2;" : "=f"(f.x), "=f"(f.y) : "l"(v));
    return f;
}

// ---------------------------------------------------------------------------
// Kernel 1: per-pixel 1x1 convs -> theta (scaled by log2 e), phi, g
// ---------------------------------------------------------------------------
__global__ __launch_bounds__(256) void prep_kernel(
    const float* __restrict__ x,
    const float* __restrict__ Wt,
    const float* __restrict__ Wp,
    const float* __restrict__ Wg)
{
    __shared__ float w[48];
    int tid = threadIdx.x;
    if (tid < 16)      w[tid]      = Wt[tid];
    else if (tid < 32) w[tid]      = Wp[tid - 16];
    else if (tid < 48) w[tid]      = Wg[tid - 32];
    __syncthreads();

    int p  = blockIdx.x * 256 + tid;      // 0 .. B*HW-1
    int b  = p >> 16;
    int hw = p & (HW - 1);
    const float* xb = x + b * (C * HW) + hw;
    float x0 = xb[0];
    float x1 = xb[HW];
    float x2 = xb[2*HW];
    float x3 = xb[3*HW];

    const float L2E = 1.4426950408889634f;

    float4 th, ph, gg;
    th.x = fmaf(w[0],  x0, fmaf(w[1],  x1, fmaf(w[2],  x2, w[3]  * x3))) * L2E;
    th.y = fmaf(w[4],  x0, fmaf(w[5],  x1, fmaf(w[6],  x2, w[7]  * x3))) * L2E;
    th.z = fmaf(w[8],  x0, fmaf(w[9],  x1, fmaf(w[10], x2, w[11] * x3))) * L2E;
    th.w = fmaf(w[12], x0, fmaf(w[13], x1, fmaf(w[14], x2, w[15] * x3))) * L2E;

    ph.x = fmaf(w[16], x0, fmaf(w[17], x1, fmaf(w[18], x2, w[19] * x3)));
    ph.y = fmaf(w[20], x0, fmaf(w[21], x1, fmaf(w[22], x2, w[23] * x3)));
    ph.z = fmaf(w[24], x0, fmaf(w[25], x1, fmaf(w[26], x2, w[27] * x3)));
    ph.w = fmaf(w[28], x0, fmaf(w[29], x1, fmaf(w[30], x2, w[31] * x3)));

    gg.x = fmaf(w[32], x0, fmaf(w[33], x1, fmaf(w[34], x2, w[35] * x3)));
    gg.y = fmaf(w[36], x0, fmaf(w[37], x1, fmaf(w[38], x2, w[39] * x3)));
    gg.z = fmaf(w[40], x0, fmaf(w[41], x1, fmaf(w[42], x2, w[43] * x3)));
    gg.w = fmaf(w[44], x0, fmaf(w[45], x1, fmaf(w[46], x2, w[47] * x3)));

    d_theta[p] = th;
    d_phi[p]   = ph;
    d_g[p]     = gg;
}

// ---------------------------------------------------------------------------
// Kernel 2: fused local non-local attention + output conv + residual.
// ki-split across two 128-thread groups; smem partial reduction.
// ---------------------------------------------------------------------------
__global__ __launch_bounds__(NTHREADS, 3) void attn_kernel(
    const float* __restrict__ x,
    const float* __restrict__ Ww,
    float* __restrict__ out)
{
    __shared__ ulonglong2 phs[HALO_H * SST];   // (phi.xy, phi.zw) packed pairs
    __shared__ ulonglong2 ggs[HALO_H * SST];
    __shared__ u64   redA[NPIX * R];
    __shared__ u64   redB[NPIX * R];
    __shared__ float redS[NPIX * R];
    __shared__ float wws[16];

    int tid = threadIdx.x;
    if (tid < 16) wws[tid] = Ww[tid];

    int b  = blockIdx.z;
    int h0 = blockIdx.y * BH;
    int w0 = blockIdx.x * BW;
    const ulonglong2* __restrict__ phg = (const ulonglong2*)(d_phi + b * HW);
    const ulonglong2* __restrict__ ggg = (const ulonglong2*)(d_g   + b * HW);

    // Cooperative halo load (zero-padded outside image), coalesced along w.
    #pragma unroll
    for (int it = 0; it < (HALO_H * HALO_W + NTHREADS - 1) / NTHREADS; it++) {
        int idx = it * NTHREADS + tid;
        if (idx < HALO_H * HALO_W) {
            int i  = idx / HALO_W;
            int j  = idx - i * HALO_W;
            int gh = h0 - PAD + i;
            int gw = w0 - PAD + j;
            ulonglong2 pv = make_ulonglong2(0ull, 0ull);
            ulonglong2 gv = make_ulonglong2(0ull, 0ull);
            if ((unsigned)gh < (unsigned)H && (unsigned)gw < (unsigned)W) {
                int g = gh * W + gw;
                pv = phg[g];
                gv = ggg[g];
            }
            phs[i * SST + j] = pv;
            ggs[i * SST + j] = gv;
        }
    }
    __syncthreads();

    // ki-split: group 0 handles window rows [0,6), group 1 handles [6,11).
    int grp    = tid >> 7;        // 0 or 1
    int wg_tid = tid & 127;       // pixel-slot id
    int ki_begin = grp ? 6 : 0;
    int ki_end   = grp ? FS : 6;

    // Lane mapping: within a warp ty = lane%4, tx = lane/4 -> conflict-free
    // LDS.128 phases given SST=43.
    int tx = (wg_tid >> 2) & 7;
    int ty = ((wg_tid >> 5) << 2) | (wg_tid & 3);
    int oh = h0 + ty;
    int ow = w0 + tx * R;

    const ulonglong2* __restrict__ thg = (const ulonglong2*)(d_theta + b * HW);

    u64 thA[R], thB[R];     // theta (x,y) and (z,w) packed, pre-scaled by log2 e
    u64 accA[R], accB[R];
    float sum[R];
    #pragma unroll
    for (int r = 0; r < R; r++) {
        ulonglong2 t = thg[oh * W + ow + r];
        thA[r] = t.x; thB[r] = t.y;
        accA[r] = 0ull; accB[r] = 0ull;
        sum[r] = 0.f;
    }

    int base = ty * SST + tx * R;

    #pragma unroll 1
    for (int ki = ki_begin; ki < ki_end; ki++) {
        const ulonglong2* prow = &phs[base + ki * SST];
        const ulonglong2* grow = &ggs[base + ki * SST];
        ulonglong2 pw[4], gw[4];
        pw[0] = prow[0]; pw[1] = prow[1]; pw[2] = prow[2];
        gw[0] = grow[0]; gw[1] = grow[1]; gw[2] = grow[2];
        #pragma unroll
        for (int kj = 0; kj < FS; kj++) {
            pw[(kj + 3) & 3] = prow[kj + 3];
            gw[(kj + 3) & 3] = grow[kj + 3];
            #pragma unroll
            for (int r = 0; r < R; r++) {
                ulonglong2 P = pw[(kj + r) & 3];
                ulonglong2 G = gw[(kj + r) & 3];
                u64 t = mul2(thA[r], P.x);
                t = fma2(thB[r], P.y, t);
                float2 f = unpack2(t);
                float e = ex2(f.x + f.y);       // theta pre-scaled by log2(e)
                u64 ee = dup2(e);
                sum[r] += e;
                accA[r] = fma2(ee, G.x, accA[r]);
                accB[r] = fma2(ee, G.y, accB[r]);
            }
        }
    }

    // Reduction: group 1 publishes partials; group 0 combines + epilogue.
    if (grp == 1) {
        #pragma unroll
        for (int r = 0; r < R; r++) {
            redA[wg_tid * R + r] = accA[r];
            redB[wg_tid * R + r] = accB[r];
            redS[wg_tid * R + r] = sum[r];
        }
    }
    __syncthreads();
    if (grp == 0) {
        const float* xb = x + b * (C * HW);
        float* ob = out + b * (C * HW);
        #pragma unroll
        for (int r = 0; r < R; r++) {
            u64 aA = add2(accA[r], redA[wg_tid * R + r]);
            u64 aB = add2(accB[r], redB[wg_tid * R + r]);
            float s = sum[r] + redS[wg_tid * R + r];
            float inv = __frcp_rn(s);
            float2 a0 = unpack2(aA);
            float2 a1 = unpack2(aB);
            float ox  = a0.x * inv;
            float oy  = a0.y * inv;
            float oz  = a1.x * inv;
            float owv = a1.y * inv;
            int pix = oh * W + ow + r;
            #pragma unroll
            for (int c = 0; c < C; c++) {
                float res = fmaf(wws[c*4+0], ox,
                            fmaf(wws[c*4+1], oy,
                            fmaf(wws[c*4+2], oz,
                                 wws[c*4+3] * owv)));
                ob[c * HW + pix] = res + xb[c * HW + pix];
            }
        }
    }
}

// ---------------------------------------------------------------------------
extern "C" void kernel_launch(void* const* d_in, const int* in_sizes, int n_in,
                              void* d_out, int out_size)
{
    const float* x  = (const float*)d_in[0];
    const float* Wt = (const float*)d_in[1];
    const float* Wp = (const float*)d_in[2];
    const float* Wg = (const float*)d_in[3];
    const float* Ww = (const float*)d_in[4];
    float* out = (float*)d_out;

    prep_kernel<<<(B * HW) / 256, 256>>>(x, Wt, Wp, Wg);

    dim3 grid(W / BW, H / BH, B);
    attn_kernel<<<grid, NTHREADS>>>(x, Ww, out);
}

// round 4
// speedup vs baseline: 1.0738x; 1.0738x over previous
#include <cuda_runtime.h>
#include <cuda_bf16.h>
#include <cstdint>

typedef unsigned long long u64;

// Problem constants
#define B 4
#define C 4
#define H 256
#define W 256
#define HW (H*W)          // 65536
#define FS 11
#define PAD 5

// Tile config for attention kernel
#define BW 32             // tile width (output pixels)
#define BH 16             // tile height
#define R  4              // pixels per thread along w
#define NPIX 128          // pixel-slots per block = (BW/R)*BH
#define NTHREADS 256      // 2 ki-groups x 128 pixel-slots
#define HALO_W (BW + FS - 1)   // 42
#define HALO_H (BH + FS - 1)   // 26
#define SST 43            // shared row stride in uint2 units (bank-skewed)

// Scratch: theta fp32 (pre-scaled by log2 e); phi/g as packed bf16x4 (uint2).
__device__ float4 d_theta[B*HW];
__device__ uint2  d_phi[B*HW];
__device__ uint2  d_g[B*HW];

__device__ __forceinline__ float ex2(float s) {
    float r;
    asm("ex2.approx.f32 %0, %1;" : "=f"(r) : "f"(s));
    return r;
}
__device__ __forceinline__ u64 fma2(u64 a, u64 b, u64 c) {
    u64 d;
    asm("fma.rn.f32x2 %0, %1, %2, %3;" : "=l"(d) : "l"(a), "l"(b), "l"(c));
    return d;
}
__device__ __forceinline__ u64 add2(u64 a, u64 b) {
    u64 d;
    asm("add.rn.f32x2 %0, %1, %2;" : "=l"(d) : "l"(a), "l"(b));
    return d;
}
__device__ __forceinline__ u64 mul2(u64 a, u64 b) {
    u64 d;
    asm("mul.rn.f32x2 %0, %1, %2;" : "=l"(d) : "l"(a), "l"(b));
    return d;
}
__device__ __forceinline__ u64 dup2(float e) {
    u64 d;
    asm("mov.b64 %0, {%1, %1};" : "=l"(d) : "f"(e));
    return d;
}
__device__ __forceinline__ float2 unpack2(u64 v) {
    float2 f;
    asm("mov.b64 {%0, %1}, %2;" : "=f"(f.x), "=f"(f.y) : "l"(v));
    return f;
}
// bf16 pair (lo,hi) -> f32x2 pair {lane0=lo, lane1=hi}. Exact (shift/mask).
__device__ __forceinline__ u64 bf2f32x2(unsigned u) {
    unsigned lo = u << 16;
    unsigned hi = u & 0xFFFF0000u;
    u64 d;
    asm("mov.b64 %0, {%1, %2};" : "=l"(d) : "r"(lo), "r"(hi));
    return d;
}
// pack (lo=a, hi=b) to bf16x2 (round-to-nearest)
__device__ __forceinline__ unsigned packbf(float a, float b) {
    unsigned r;
    asm("cvt.rn.satfinite.bf16x2.f32 %0, %1, %2;" : "=r"(r) : "f"(b), "f"(a));
    return r;
}

// ---------------------------------------------------------------------------
// Kernel 1: per-pixel 1x1 convs -> theta (scaled by log2 e), phi, g (bf16)
// ---------------------------------------------------------------------------
__global__ __launch_bounds__(256) void prep_kernel(
    const float* __restrict__ x,
    const float* __restrict__ Wt,
    const float* __restrict__ Wp,
    const float* __restrict__ Wg)
{
    __shared__ float w[48];
    int tid = threadIdx.x;
    if (tid < 16)      w[tid]      = Wt[tid];
    else if (tid < 32) w[tid]      = Wp[tid - 16];
    else if (tid < 48) w[tid]      = Wg[tid - 32];
    __syncthreads();

    int p  = blockIdx.x * 256 + tid;      // 0 .. B*HW-1
    int b  = p >> 16;
    int hw = p & (HW - 1);
    const float* xb = x + b * (C * HW) + hw;
    float x0 = xb[0];
    float x1 = xb[HW];
    float x2 = xb[2*HW];
    float x3 = xb[3*HW];

    const float L2E = 1.4426950408889634f;

    float4 th, ph, gg;
    th.x = fmaf(w[0],  x0, fmaf(w[1],  x1, fmaf(w[2],  x2, w[3]  * x3))) * L2E;
    th.y = fmaf(w[4],  x0, fmaf(w[5],  x1, fmaf(w[6],  x2, w[7]  * x3))) * L2E;
    th.z = fmaf(w[8],  x0, fmaf(w[9],  x1, fmaf(w[10], x2, w[11] * x3))) * L2E;
    th.w = fmaf(w[12], x0, fmaf(w[13], x1, fmaf(w[14], x2, w[15] * x3))) * L2E;

    ph.x = fmaf(w[16], x0, fmaf(w[17], x1, fmaf(w[18], x2, w[19] * x3)));
    ph.y = fmaf(w[20], x0, fmaf(w[21], x1, fmaf(w[22], x2, w[23] * x3)));
    ph.z = fmaf(w[24], x0, fmaf(w[25], x1, fmaf(w[26], x2, w[27] * x3)));
    ph.w = fmaf(w[28], x0, fmaf(w[29], x1, fmaf(w[30], x2, w[31] * x3)));

    gg.x = fmaf(w[32], x0, fmaf(w[33], x1, fmaf(w[34], x2, w[35] * x3)));
    gg.y = fmaf(w[36], x0, fmaf(w[37], x1, fmaf(w[38], x2, w[39] * x3)));
    gg.z = fmaf(w[40], x0, fmaf(w[41], x1, fmaf(w[42], x2, w[43] * x3)));
    gg.w = fmaf(w[44], x0, fmaf(w[45], x1, fmaf(w[46], x2, w[47] * x3)));

    d_theta[p] = th;
    d_phi[p]   = make_uint2(packbf(ph.x, ph.y), packbf(ph.z, ph.w));
    d_g[p]     = make_uint2(packbf(gg.x, gg.y), packbf(gg.z, gg.w));
}

// ---------------------------------------------------------------------------
// Kernel 2: fused local non-local attention + output conv + residual.
// bf16 shared tiles (halved crossbar traffic); 2-way ki-split; f32 math.
// ---------------------------------------------------------------------------
__global__ __launch_bounds__(NTHREADS, 3) void attn_kernel(
    const float* __restrict__ x,
    const float* __restrict__ Ww,
    float* __restrict__ out)
{
    __shared__ uint2 phs[HALO_H * SST];   // bf16x4 per pixel: (ch01, ch23)
    __shared__ uint2 ggs[HALO_H * SST];
    __shared__ u64   redA[NPIX * R];
    __shared__ u64   redB[NPIX * R];
    __shared__ float redS[NPIX * R];
    __shared__ float wws[16];

    int tid = threadIdx.x;
    if (tid < 16) wws[tid] = Ww[tid];

    int b  = blockIdx.z;
    int h0 = blockIdx.y * BH;
    int w0 = blockIdx.x * BW;
    const uint2* __restrict__ phg = d_phi + b * HW;
    const uint2* __restrict__ ggg = d_g   + b * HW;

    // Cooperative halo load (zero-padded outside image), coalesced along w.
    #pragma unroll
    for (int it = 0; it < (HALO_H * HALO_W + NTHREADS - 1) / NTHREADS; it++) {
        int idx = it * NTHREADS + tid;
        if (idx < HALO_H * HALO_W) {
            int i  = idx / HALO_W;
            int j  = idx - i * HALO_W;
            int gh = h0 - PAD + i;
            int gw = w0 - PAD + j;
            uint2 pv = make_uint2(0u, 0u);
            uint2 gv = make_uint2(0u, 0u);
            if ((unsigned)gh < (unsigned)H && (unsigned)gw < (unsigned)W) {
                int g = gh * W + gw;
                pv = phg[g];
                gv = ggg[g];
            }
            phs[i * SST + j] = pv;
            ggs[i * SST + j] = gv;
        }
    }
    __syncthreads();

    // ki-split: group 0 rows [0,5) + epilogue; group 1 rows [5,11).
    int grp    = tid >> 7;        // 0 or 1
    int wg_tid = tid & 127;       // pixel-slot id
    int ki_begin = grp ? 5 : 0;
    int ki_end   = grp ? FS : 5;

    // Lane mapping: ty = lane%4, tx = lane/4 -> conflict-free LDS.64 phases.
    int tx = (wg_tid >> 2) & 7;
    int ty = ((wg_tid >> 5) << 2) | (wg_tid & 3);
    int oh = h0 + ty;
    int ow = w0 + tx * R;

    const ulonglong2* __restrict__ thg = (const ulonglong2*)(d_theta + b * HW);

    u64 thA[R], thB[R];     // theta (x,y),(z,w) packed f32x2, pre-scaled log2e
    u64 accA[R], accB[R];
    float sum[R];
    #pragma unroll
    for (int r = 0; r < R; r++) {
        ulonglong2 t = thg[oh * W + ow + r];
        thA[r] = t.x; thB[r] = t.y;
        accA[r] = 0ull; accB[r] = 0ull;
        sum[r] = 0.f;
    }

    int base = ty * SST + tx * R;

    #pragma unroll 1
    for (int ki = ki_begin; ki < ki_end; ki++) {
        const uint2* prow = &phs[base + ki * SST];
        const uint2* grow = &ggs[base + ki * SST];
        // 4-entry sliding windows of converted f32x2 pairs
        u64 pA[4], pB[4], gA[4], gB[4];
        #pragma unroll
        for (int j = 0; j < 3; j++) {
            uint2 pv = prow[j];
            uint2 gv = grow[j];
            pA[j] = bf2f32x2(pv.x); pB[j] = bf2f32x2(pv.y);
            gA[j] = bf2f32x2(gv.x); gB[j] = bf2f32x2(gv.y);
        }
        #pragma unroll
        for (int kj = 0; kj < FS; kj++) {
            int s = (kj + 3) & 3;
            uint2 pv = prow[kj + 3];
            uint2 gv = grow[kj + 3];
            pA[s] = bf2f32x2(pv.x); pB[s] = bf2f32x2(pv.y);
            gA[s] = bf2f32x2(gv.x); gB[s] = bf2f32x2(gv.y);
            #pragma unroll
            for (int r = 0; r < R; r++) {
                int q = (kj + r) & 3;
                u64 t = mul2(thA[r], pA[q]);
                t = fma2(thB[r], pB[q], t);
                float2 f = unpack2(t);
                float e = ex2(f.x + f.y);       // theta pre-scaled by log2 e
                u64 ee = dup2(e);
                sum[r] += e;
                accA[r] = fma2(ee, gA[q], accA[r]);
                accB[r] = fma2(ee, gB[q], accB[r]);
            }
        }
    }

    // Reduction: group 1 publishes partials; group 0 combines + epilogue.
    if (grp == 1) {
        #pragma unroll
        for (int r = 0; r < R; r++) {
            redA[wg_tid * R + r] = accA[r];
            redB[wg_tid * R + r] = accB[r];
            redS[wg_tid * R + r] = sum[r];
        }
    }
    __syncthreads();
    if (grp == 0) {
        const float* xb = x + b * (C * HW);
        float* ob = out + b * (C * HW);
        #pragma unroll
        for (int r = 0; r < R; r++) {
            u64 aA = add2(accA[r], redA[wg_tid * R + r]);
            u64 aB = add2(accB[r], redB[wg_tid * R + r]);
            float s = sum[r] + redS[wg_tid * R + r];
            float inv = __frcp_rn(s);
            float2 a0 = unpack2(aA);
            float2 a1 = unpack2(aB);
            float ox  = a0.x * inv;
            float oy  = a0.y * inv;
            float oz  = a1.x * inv;
            float owv = a1.y * inv;
            int pix = oh * W + ow + r;
            #pragma unroll
            for (int c = 0; c < C; c++) {
                float res = fmaf(wws[c*4+0], ox,
                            fmaf(wws[c*4+1], oy,
                            fmaf(wws[c*4+2], oz,
                                 wws[c*4+3] * owv)));
                ob[c * HW + pix] = res + xb[c * HW + pix];
            }
        }
    }
}

// ---------------------------------------------------------------------------
extern "C" void kernel_launch(void* const* d_in, const int* in_sizes, int n_in,
                              void* d_out, int out_size)
{
    const float* x  = (const float*)d_in[0];
    const float* Wt = (const float*)d_in[1];
    const float* Wp = (const float*)d_in[2];
    const float* Wg = (const float*)d_in[3];
    const float* Ww = (const float*)d_in[4];
    float* out = (float*)d_out;

    prep_kernel<<<(B * HW) / 256, 256>>>(x, Wt, Wp, Wg);

    dim3 grid(W / BW, H / BH, B);
    attn_kernel<<<grid, NTHREADS>>>(x, Ww, out);
}

// round 5
// speedup vs baseline: 1.3372x; 1.2452x over previous
#include <cuda_runtime.h>
#include <cuda_bf16.h>
#include <cstdint>

typedef unsigned long long u64;

// Problem constants
#define B 4
#define C 4
#define H 256
#define W 256
#define HW (H*W)          // 65536
#define FS 11
#define PAD 5

// Tile config
#define BW 32             // tile width (output pixels)
#define BH 8              // tile height
#define R  4              // pixels per thread along w
#define NTHREADS 64       // (BW/R) * BH = 8 * 8
#define HALO_W (BW + FS - 1)   // 42
#define HALO_H (BH + FS - 1)   // 18
#define NHALO (HALO_H * HALO_W)  // 756
#define SST 43            // shared row stride in 16B units (bank-skewed)

__device__ __forceinline__ float ex2(float s) {
    float r;
    asm("ex2.approx.f32 %0, %1;" : "=f"(r) : "f"(s));
    return r;
}
__device__ __forceinline__ u64 fma2(u64 a, u64 b, u64 c) {
    u64 d;
    asm("fma.rn.f32x2 %0, %1, %2, %3;" : "=l"(d) : "l"(a), "l"(b), "l"(c));
    return d;
}
__device__ __forceinline__ u64 mul2(u64 a, u64 b) {
    u64 d;
    asm("mul.rn.f32x2 %0, %1, %2;" : "=l"(d) : "l"(a), "l"(b));
    return d;
}
__device__ __forceinline__ u64 dup2(float e) {
    u64 d;
    asm("mov.b64 %0, {%1, %1};" : "=l"(d) : "f"(e));
    return d;
}
__device__ __forceinline__ u64 packf2(float a, float b) {
    u64 d;
    asm("mov.b64 %0, {%1, %2};" : "=l"(d) : "f"(a), "f"(b));
    return d;
}
__device__ __forceinline__ float2 unpack2(u64 v) {
    float2 f;
    asm("mov.b64 {%0, %1}, %2;" : "=f"(f.x), "=f"(f.y) : "l"(v));
    return f;
}

// ---------------------------------------------------------------------------
// Single fused kernel: per-block halo prep (phi, g) + theta + local attention
// + output conv + residual.
// ---------------------------------------------------------------------------
__global__ __launch_bounds__(NTHREADS) void fused_kernel(
    const float* __restrict__ x,
    const float* __restrict__ Wt,
    const float* __restrict__ Wp,
    const float* __restrict__ Wg,
    const float* __restrict__ Ww,
    float* __restrict__ out)
{
    __shared__ ulonglong2 phs[HALO_H * SST];   // phi: (xy, zw) f32 pairs
    __shared__ ulonglong2 ggs[HALO_H * SST];   // g  : (xy, zw) f32 pairs
    __shared__ float wts[48];                  // Wt | Wp | Wg
    __shared__ float wws[16];

    int tid = threadIdx.x;
    if (tid < 48) wts[tid] = (tid < 16) ? Wt[tid]
                           : (tid < 32) ? Wp[tid - 16]
                                        : Wg[tid - 32];
    if (tid < 16) wws[tid] = Ww[tid];
    __syncthreads();

    int b  = blockIdx.z;
    int h0 = blockIdx.y * BH;
    int w0 = blockIdx.x * BW;
    const float* xb = x + b * (C * HW);

    // --- Fused halo prep: compute phi & g for the (18 x 42) halo ---
    #pragma unroll
    for (int it = 0; it < (NHALO + NTHREADS - 1) / NTHREADS; it++) {
        int idx = it * NTHREADS + tid;
        if (idx < NHALO) {
            int i  = idx / HALO_W;
            int j  = idx - i * HALO_W;
            int gh = h0 - PAD + i;
            int gw = w0 - PAD + j;
            ulonglong2 pv = make_ulonglong2(0ull, 0ull);
            ulonglong2 gv = make_ulonglong2(0ull, 0ull);
            if ((unsigned)gh < (unsigned)H && (unsigned)gw < (unsigned)W) {
                const float* xp = xb + gh * W + gw;
                float x0 = xp[0];
                float x1 = xp[HW];
                float x2 = xp[2*HW];
                float x3 = xp[3*HW];
                float p0 = fmaf(wts[16], x0, fmaf(wts[17], x1, fmaf(wts[18], x2, wts[19] * x3)));
                float p1 = fmaf(wts[20], x0, fmaf(wts[21], x1, fmaf(wts[22], x2, wts[23] * x3)));
                float p2 = fmaf(wts[24], x0, fmaf(wts[25], x1, fmaf(wts[26], x2, wts[27] * x3)));
                float p3 = fmaf(wts[28], x0, fmaf(wts[29], x1, fmaf(wts[30], x2, wts[31] * x3)));
                float g0 = fmaf(wts[32], x0, fmaf(wts[33], x1, fmaf(wts[34], x2, wts[35] * x3)));
                float g1 = fmaf(wts[36], x0, fmaf(wts[37], x1, fmaf(wts[38], x2, wts[39] * x3)));
                float g2 = fmaf(wts[40], x0, fmaf(wts[41], x1, fmaf(wts[42], x2, wts[43] * x3)));
                float g3 = fmaf(wts[44], x0, fmaf(wts[45], x1, fmaf(wts[46], x2, wts[47] * x3)));
                pv = make_ulonglong2(packf2(p0, p1), packf2(p2, p3));
                gv = make_ulonglong2(packf2(g0, g1), packf2(g2, g3));
            }
            phs[i * SST + j] = pv;
            ggs[i * SST + j] = gv;
        }
    }

    // --- Theta for this thread's 4 pixels (computed while halo fills) ---
    // Lane mapping: ty = lane%4(+4 for warp1), tx = (tid>>2)&7 -> conflict-free
    // LDS.128 phases given SST=43 (same pattern as the proven R1 kernel).
    int tx = (tid >> 2) & 7;
    int ty = ((tid >> 5) << 2) | (tid & 3);
    int oh = h0 + ty;
    int ow = w0 + tx * R;
    int pixbase = oh * W + ow;

    const float L2E = 1.4426950408889634f;
    float xs[4][4];
    #pragma unroll
    for (int c = 0; c < 4; c++) {
        float4 v = *(const float4*)(xb + c * HW + pixbase);
        xs[c][0] = v.x; xs[c][1] = v.y; xs[c][2] = v.z; xs[c][3] = v.w;
    }

    u64 thA[R], thB[R];     // theta (c0,c1),(c2,c3) packed f32x2, scaled log2e
    u64 accA[R], accB[R];
    float sum[R];
    #pragma unroll
    for (int r = 0; r < R; r++) {
        float t0 = fmaf(wts[0],  xs[0][r], fmaf(wts[1],  xs[1][r], fmaf(wts[2],  xs[2][r], wts[3]  * xs[3][r]))) * L2E;
        float t1 = fmaf(wts[4],  xs[0][r], fmaf(wts[5],  xs[1][r], fmaf(wts[6],  xs[2][r], wts[7]  * xs[3][r]))) * L2E;
        float t2 = fmaf(wts[8],  xs[0][r], fmaf(wts[9],  xs[1][r], fmaf(wts[10], xs[2][r], wts[11] * xs[3][r]))) * L2E;
        float t3 = fmaf(wts[12], xs[0][r], fmaf(wts[13], xs[1][r], fmaf(wts[14], xs[2][r], wts[15] * xs[3][r]))) * L2E;
        thA[r] = packf2(t0, t1);
        thB[r] = packf2(t2, t3);
        accA[r] = 0ull; accB[r] = 0ull;
        sum[r] = 0.f;
    }
    __syncthreads();

    // --- Main attention loop (identical structure to best-known R1 loop) ---
    int base = ty * SST + tx * R;

    #pragma unroll 1
    for (int ki = 0; ki < FS; ki++) {
        const ulonglong2* prow = &phs[base + ki * SST];
        const ulonglong2* grow = &ggs[base + ki * SST];
        ulonglong2 pw[4], gw[4];
        pw[0] = prow[0]; pw[1] = prow[1]; pw[2] = prow[2];
        gw[0] = grow[0]; gw[1] = grow[1]; gw[2] = grow[2];
        #pragma unroll
        for (int kj = 0; kj < FS; kj++) {
            pw[(kj + 3) & 3] = prow[kj + 3];
            gw[(kj + 3) & 3] = grow[kj + 3];
            #pragma unroll
            for (int r = 0; r < R; r++) {
                ulonglong2 P = pw[(kj + r) & 3];
                ulonglong2 G = gw[(kj + r) & 3];
                u64 t = mul2(thA[r], P.x);
                t = fma2(thB[r], P.y, t);
                float2 f = unpack2(t);
                float e = ex2(f.x + f.y);       // theta pre-scaled by log2 e
                u64 ee = dup2(e);
                sum[r] += e;
                accA[r] = fma2(ee, G.x, accA[r]);
                accB[r] = fma2(ee, G.y, accB[r]);
            }
        }
    }

    // --- Epilogue: normalize, 1x1 conv with Ww, residual; float4 stores ---
    float ox[R], oy[R], oz[R], owv[R];
    #pragma unroll
    for (int r = 0; r < R; r++) {
        float inv = __frcp_rn(sum[r]);
        float2 a0 = unpack2(accA[r]);
        float2 a1 = unpack2(accB[r]);
        ox[r]  = a0.x * inv;
        oy[r]  = a0.y * inv;
        oz[r]  = a1.x * inv;
        owv[r] = a1.y * inv;
    }
    float* ob = out + b * (C * HW);
    #pragma unroll
    for (int c = 0; c < C; c++) {
        float4 res;
        res.x = fmaf(wws[c*4+0], ox[0], fmaf(wws[c*4+1], oy[0], fmaf(wws[c*4+2], oz[0], wws[c*4+3] * owv[0]))) + xs[c][0];
        res.y = fmaf(wws[c*4+0], ox[1], fmaf(wws[c*4+1], oy[1], fmaf(wws[c*4+2], oz[1], wws[c*4+3] * owv[1]))) + xs[c][1];
        res.z = fmaf(wws[c*4+0], ox[2], fmaf(wws[c*4+1], oy[2], fmaf(wws[c*4+2], oz[2], wws[c*4+3] * owv[2]))) + xs[c][2];
        res.w = fmaf(wws[c*4+0], ox[3], fmaf(wws[c*4+1], oy[3], fmaf(wws[c*4+2], oz[3], wws[c*4+3] * owv[3]))) + xs[c][3];
        *(float4*)(ob + c * HW + pixbase) = res;
    }
}

// ---------------------------------------------------------------------------
extern "C" void kernel_launch(void* const* d_in, const int* in_sizes, int n_in,
                              void* d_out, int out_size)
{
    const float* x  = (const float*)d_in[0];
    const float* Wt = (const float*)d_in[1];
    const float* Wp = (const float*)d_in[2];
    const float* Wg = (const float*)d_in[3];
    const float* Ww = (const float*)d_in[4];
    float* out = (float*)d_out;

    dim3 grid(W / BW, H / BH, B);
    fused_kernel<<<grid, NTHREADS>>>(x, Wt, Wp, Wg, Ww, out);
}

// round 6
// speedup vs baseline: 1.3960x; 1.0440x over previous
#include <cuda_runtime.h>
#include <cuda_bf16.h>
#include <cstdint>

typedef unsigned long long u64;

// Problem constants
#define B 4
#define C 4
#define H 256
#define W 256
#define HW (H*W)          // 65536
#define FS 11
#define PAD 5

// Tile config
#define BW 32             // tile width (output pixels)
#define BH 8              // tile height
#define R  2              // pixels per thread along w
#define NTHREADS 128      // (BW/R) * BH = 16 * 8
#define HALO_W (BW + FS - 1)   // 42
#define HALO_H (BH + FS - 1)   // 18
#define NHALO (HALO_H * HALO_W)  // 756
#define SST 43            // shared row stride in 16B units (bank-skewed)

__device__ __forceinline__ float ex2(float s) {
    float r;
    asm("ex2.approx.f32 %0, %1;" : "=f"(r) : "f"(s));
    return r;
}
__device__ __forceinline__ u64 fma2(u64 a, u64 b, u64 c) {
    u64 d;
    asm("fma.rn.f32x2 %0, %1, %2, %3;" : "=l"(d) : "l"(a), "l"(b), "l"(c));
    return d;
}
__device__ __forceinline__ u64 mul2(u64 a, u64 b) {
    u64 d;
    asm("mul.rn.f32x2 %0, %1, %2;" : "=l"(d) : "l"(a), "l"(b));
    return d;
}
__device__ __forceinline__ u64 dup2(float e) {
    u64 d;
    asm("mov.b64 %0, {%1, %1};" : "=l"(d) : "f"(e));
    return d;
}
__device__ __forceinline__ u64 packf2(float a, float b) {
    u64 d;
    asm("mov.b64 %0, {%1, %2};" : "=l"(d) : "f"(a), "f"(b));
    return d;
}
__device__ __forceinline__ float2 unpack2(u64 v) {
    float2 f;
    asm("mov.b64 {%0, %1}, %2;" : "=f"(f.x), "=f"(f.y) : "l"(v));
    return f;
}

// ---------------------------------------------------------------------------
// Single fused kernel, algebraically folded:
//   score_k = psi . x_k   with  psi = (Wp^T Wt) x_p  (pre-scaled by log2 e)
//   out     = M (sum_k att_k x_k) + x,  M = Ww Wg
// Shared memory holds only the raw x halo (4 channels packed as 2x f32x2).
// ---------------------------------------------------------------------------
__global__ __launch_bounds__(NTHREADS) void fused_kernel(
    const float* __restrict__ x,
    const float* __restrict__ Wt,
    const float* __restrict__ Wp,
    const float* __restrict__ Wg,
    const float* __restrict__ Ww,
    float* __restrict__ out)
{
    __shared__ ulonglong2 xsh[HALO_H * SST];   // x halo: (c01, c23) f32 pairs
    __shared__ float wN[16];                   // N = Wp^T Wt, scaled by log2 e
    __shared__ float wM[16];                   // M = Ww Wg

    int tid = threadIdx.x;

    int b  = blockIdx.z;
    int h0 = blockIdx.y * BH;
    int w0 = blockIdx.x * BW;
    const float* xb = x + b * (C * HW);

    // --- Small matrix products N, M (threads 0..31, one entry each) ---
    if (tid < 32) {
        int e = tid & 15;
        int i = e >> 2;       // row
        int j = e & 3;        // col
        if (tid < 16) {
            // N[i][j] = sum_o Wp[o*4+i] * Wt[o*4+j], scaled by log2(e)
            float s = Wp[i] * Wt[j];
            s = fmaf(Wp[4 + i],  Wt[4 + j],  s);
            s = fmaf(Wp[8 + i],  Wt[8 + j],  s);
            s = fmaf(Wp[12 + i], Wt[12 + j], s);
            wN[e] = s * 1.4426950408889634f;
        } else {
            // M[i][j] = sum_c Ww[i*4+c] * Wg[c*4+j]
            float s = Ww[i*4 + 0] * Wg[j];
            s = fmaf(Ww[i*4 + 1], Wg[4 + j],  s);
            s = fmaf(Ww[i*4 + 2], Wg[8 + j],  s);
            s = fmaf(Ww[i*4 + 3], Wg[12 + j], s);
            wM[e] = s;
        }
    }

    // --- Halo copy: raw x (4 channels) into shared, zero-padded ---
    #pragma unroll
    for (int it = 0; it < (NHALO + NTHREADS - 1) / NTHREADS; it++) {
        int idx = it * NTHREADS + tid;
        if (idx < NHALO) {
            int i  = idx / HALO_W;
            int j  = idx - i * HALO_W;
            int gh = h0 - PAD + i;
            int gw = w0 - PAD + j;
            ulonglong2 v = make_ulonglong2(0ull, 0ull);
            if ((unsigned)gh < (unsigned)H && (unsigned)gw < (unsigned)W) {
                const float* xp = xb + gh * W + gw;
                v = make_ulonglong2(packf2(xp[0],    xp[HW]),
                                    packf2(xp[2*HW], xp[3*HW]));
            }
            xsh[i * SST + j] = v;
        }
    }

    // --- Own-pixel x loads (needed for psi and residual) ---
    // Lane mapping: ty = lane&1 (+2 per warp), tx = (lane>>1)&15.
    // Conflict-free 8-lane LDS.128 phases given SST=43.
    int tx = (tid >> 1) & 15;
    int ty = ((tid >> 5) << 1) | (tid & 1);
    int oh = h0 + ty;
    int ow = w0 + tx * R;
    int pixbase = oh * W + ow;

    float xs[4][R];
    #pragma unroll
    for (int c = 0; c < 4; c++) {
        float2 v = *(const float2*)(xb + c * HW + pixbase);
        xs[c][0] = v.x; xs[c][1] = v.y;
    }
    __syncthreads();

    // --- psi = N x_p (per own pixel), packed as f32x2 pairs ---
    u64 psiA[R], psiB[R];
    u64 accA[R], accB[R];
    float sum[R];
    #pragma unroll
    for (int r = 0; r < R; r++) {
        float p0 = fmaf(wN[0],  xs[0][r], fmaf(wN[1],  xs[1][r], fmaf(wN[2],  xs[2][r], wN[3]  * xs[3][r])));
        float p1 = fmaf(wN[4],  xs[0][r], fmaf(wN[5],  xs[1][r], fmaf(wN[6],  xs[2][r], wN[7]  * xs[3][r])));
        float p2 = fmaf(wN[8],  xs[0][r], fmaf(wN[9],  xs[1][r], fmaf(wN[10], xs[2][r], wN[11] * xs[3][r])));
        float p3 = fmaf(wN[12], xs[0][r], fmaf(wN[13], xs[1][r], fmaf(wN[14], xs[2][r], wN[15] * xs[3][r])));
        psiA[r] = packf2(p0, p1);
        psiB[r] = packf2(p2, p3);
        accA[r] = 0ull; accB[r] = 0ull;
        sum[r] = 0.f;
    }

    // --- Main attention loop: one shared array, score and acc share X ---
    int base = ty * SST + tx * R;

    #pragma unroll 1
    for (int ki = 0; ki < FS; ki++) {
        const ulonglong2* row = &xsh[base + ki * SST];
        ulonglong2 xw[4];
        xw[0] = row[0]; xw[1] = row[1]; xw[2] = row[2];
        #pragma unroll
        for (int kj = 0; kj < FS; kj++) {
            if (kj < 9) xw[(kj + 3) & 3] = row[kj + 3];   // compile-time guard
            #pragma unroll
            for (int r = 0; r < R; r++) {
                ulonglong2 X = xw[(kj + r) & 3];
                u64 t = mul2(psiA[r], X.x);
                t = fma2(psiB[r], X.y, t);
                float2 f = unpack2(t);
                float e = ex2(f.x + f.y);       // psi pre-scaled by log2 e
                u64 ee = dup2(e);
                sum[r] += e;
                accA[r] = fma2(ee, X.x, accA[r]);
                accB[r] = fma2(ee, X.y, accB[r]);
            }
        }
    }

    // --- Epilogue: normalize, apply M, residual; float2 stores ---
    float a0[R], a1[R], a2[R], a3[R];
    #pragma unroll
    for (int r = 0; r < R; r++) {
        float inv = __frcp_rn(sum[r]);
        float2 fA = unpack2(accA[r]);
        float2 fB = unpack2(accB[r]);
        a0[r] = fA.x * inv;
        a1[r] = fA.y * inv;
        a2[r] = fB.x * inv;
        a3[r] = fB.y * inv;
    }
    float* ob = out + b * (C * HW);
    #pragma unroll
    for (int c = 0; c < C; c++) {
        float2 res;
        res.x = fmaf(wM[c*4+0], a0[0], fmaf(wM[c*4+1], a1[0], fmaf(wM[c*4+2], a2[0], wM[c*4+3] * a3[0]))) + xs[c][0];
        res.y = fmaf(wM[c*4+0], a0[1], fmaf(wM[c*4+1], a1[1], fmaf(wM[c*4+2], a2[1], wM[c*4+3] * a3[1]))) + xs[c][1];
        *(float2*)(ob + c * HW + pixbase) = res;
    }
}

// ---------------------------------------------------------------------------
extern "C" void kernel_launch(void* const* d_in, const int* in_sizes, int n_in,
                              void* d_out, int out_size)
{
    const float* x  = (const float*)d_in[0];
    const float* Wt = (const float*)d_in[1];
    const float* Wp = (const float*)d_in[2];
    const float* Wg = (const float*)d_in[3];
    const float* Ww = (const float*)d_in[4];
    float* out = (float*)d_out;

    dim3 grid(W / BW, H / BH, B);
    fused_kernel<<<grid, NTHREADS>>>(x, Wt, Wp, Wg, Ww, out);
}

// round 7
// speedup vs baseline: 1.4562x; 1.0431x over previous
#include <cuda_runtime.h>
#include <cuda_bf16.h>
#include <cstdint>

typedef unsigned long long u64;

// Problem constants
#define B 4
#define C 4
#define H 256
#define W 256
#define HW (H*W)          // 65536
#define FS 11
#define PAD 5

// Tile config
#define BW 32             // tile width (output pixels)
#define BH 8              // tile height
#define R  2              // pixels per thread along w
#define NTHREADS 128      // (BW/R) * BH = 16 * 8
#define HALO_W (BW + FS - 1)   // 42
#define HALO_H (BH + FS - 1)   // 18
#define NHALO (HALO_H * HALO_W)  // 756
#define SST 43            // shared row stride in 16B units (bank-skewed)

__device__ __forceinline__ float ex2(float s) {
    float r;
    asm("ex2.approx.f32 %0, %1;" : "=f"(r) : "f"(s));
    return r;
}
__device__ __forceinline__ u64 fma2(u64 a, u64 b, u64 c) {
    u64 d;
    asm("fma.rn.f32x2 %0, %1, %2, %3;" : "=l"(d) : "l"(a), "l"(b), "l"(c));
    return d;
}
__device__ __forceinline__ u64 mul2(u64 a, u64 b) {
    u64 d;
    asm("mul.rn.f32x2 %0, %1, %2;" : "=l"(d) : "l"(a), "l"(b));
    return d;
}
__device__ __forceinline__ u64 dup2(float e) {
    u64 d;
    asm("mov.b64 %0, {%1, %1};" : "=l"(d) : "f"(e));
    return d;
}
__device__ __forceinline__ u64 packf2(float a, float b) {
    u64 d;
    asm("mov.b64 %0, {%1, %2};" : "=l"(d) : "f"(a), "f"(b));
    return d;
}
__device__ __forceinline__ float2 unpack2(u64 v) {
    float2 f;
    asm("mov.b64 {%0, %1}, %2;" : "=f"(f.x), "=f"(f.y) : "l"(v));
    return f;
}

// ---------------------------------------------------------------------------
// Single fused kernel, algebraically folded:
//   score_k = psi . x_k   with  psi = (Wp^T Wt) x_p  (pre-scaled by log2 e)
//   out     = M (sum_k att_k x_k) + x,  M = Ww Wg
// Main loop processes TWO window rows per outer iteration -> 4 independent
// dependency chains per inner step (2 rows x 2 pixels).
// ---------------------------------------------------------------------------
__global__ __launch_bounds__(NTHREADS) void fused_kernel(
    const float* __restrict__ x,
    const float* __restrict__ Wt,
    const float* __restrict__ Wp,
    const float* __restrict__ Wg,
    const float* __restrict__ Ww,
    float* __restrict__ out)
{
    __shared__ ulonglong2 xsh[HALO_H * SST];   // x halo: (c01, c23) f32 pairs
    __shared__ float wN[16];                   // N = Wp^T Wt, scaled by log2 e
    __shared__ float wM[16];                   // M = Ww Wg

    int tid = threadIdx.x;

    int b  = blockIdx.z;
    int h0 = blockIdx.y * BH;
    int w0 = blockIdx.x * BW;
    const float* xb = x + b * (C * HW);

    // --- Small matrix products N, M (threads 0..31, one entry each) ---
    if (tid < 32) {
        int e = tid & 15;
        int i = e >> 2;       // row
        int j = e & 3;        // col
        if (tid < 16) {
            float s = Wp[i] * Wt[j];
            s = fmaf(Wp[4 + i],  Wt[4 + j],  s);
            s = fmaf(Wp[8 + i],  Wt[8 + j],  s);
            s = fmaf(Wp[12 + i], Wt[12 + j], s);
            wN[e] = s * 1.4426950408889634f;
        } else {
            float s = Ww[i*4 + 0] * Wg[j];
            s = fmaf(Ww[i*4 + 1], Wg[4 + j],  s);
            s = fmaf(Ww[i*4 + 2], Wg[8 + j],  s);
            s = fmaf(Ww[i*4 + 3], Wg[12 + j], s);
            wM[e] = s;
        }
    }

    // --- Halo copy: raw x (4 channels) into shared, zero-padded ---
    #pragma unroll
    for (int it = 0; it < (NHALO + NTHREADS - 1) / NTHREADS; it++) {
        int idx = it * NTHREADS + tid;
        if (idx < NHALO) {
            int i  = idx / HALO_W;
            int j  = idx - i * HALO_W;
            int gh = h0 - PAD + i;
            int gw = w0 - PAD + j;
            ulonglong2 v = make_ulonglong2(0ull, 0ull);
            if ((unsigned)gh < (unsigned)H && (unsigned)gw < (unsigned)W) {
                const float* xp = xb + gh * W + gw;
                v = make_ulonglong2(packf2(xp[0],    xp[HW]),
                                    packf2(xp[2*HW], xp[3*HW]));
            }
            xsh[i * SST + j] = v;
        }
    }

    // --- Own-pixel x loads (for psi and residual) ---
    // Lane mapping: ty = lane&1 (+2 per warp), tx = (lane>>1)&15.
    // Conflict-free 8-lane LDS.128 phases given SST=43.
    int tx = (tid >> 1) & 15;
    int ty = ((tid >> 5) << 1) | (tid & 1);
    int oh = h0 + ty;
    int ow = w0 + tx * R;
    int pixbase = oh * W + ow;

    float xs[4][R];
    #pragma unroll
    for (int c = 0; c < 4; c++) {
        float2 v = *(const float2*)(xb + c * HW + pixbase);
        xs[c][0] = v.x; xs[c][1] = v.y;
    }
    __syncthreads();

    // --- psi = N x_p (per own pixel), packed as f32x2 pairs ---
    u64 psiA[R], psiB[R];
    u64 accA[R], accB[R];
    float sum[R];
    #pragma unroll
    for (int r = 0; r < R; r++) {
        float p0 = fmaf(wN[0],  xs[0][r], fmaf(wN[1],  xs[1][r], fmaf(wN[2],  xs[2][r], wN[3]  * xs[3][r])));
        float p1 = fmaf(wN[4],  xs[0][r], fmaf(wN[5],  xs[1][r], fmaf(wN[6],  xs[2][r], wN[7]  * xs[3][r])));
        float p2 = fmaf(wN[8],  xs[0][r], fmaf(wN[9],  xs[1][r], fmaf(wN[10], xs[2][r], wN[11] * xs[3][r])));
        float p3 = fmaf(wN[12], xs[0][r], fmaf(wN[13], xs[1][r], fmaf(wN[14], xs[2][r], wN[15] * xs[3][r])));
        psiA[r] = packf2(p0, p1);
        psiB[r] = packf2(p2, p3);
        accA[r] = 0ull; accB[r] = 0ull;
        sum[r] = 0.f;
    }

    int base = ty * SST + tx * R;

    // --- Main loop: two window rows per outer iteration (4 indep chains) ---
    #pragma unroll 1
    for (int kp = 0; kp < 5; kp++) {
        const ulonglong2* row0 = &xsh[base + (2 * kp) * SST];
        const ulonglong2* row1 = row0 + SST;
        ulonglong2 aw[4], bw[4];
        aw[0] = row0[0]; aw[1] = row0[1]; aw[2] = row0[2];
        bw[0] = row1[0]; bw[1] = row1[1]; bw[2] = row1[2];
        #pragma unroll
        for (int kj = 0; kj < FS; kj++) {
            if (kj < 9) {
                aw[(kj + 3) & 3] = row0[kj + 3];
                bw[(kj + 3) & 3] = row1[kj + 3];
            }
            #pragma unroll
            for (int r = 0; r < R; r++) {
                int q = (kj + r) & 3;
                ulonglong2 Xa = aw[q];
                ulonglong2 Xb = bw[q];
                u64 ta = mul2(psiA[r], Xa.x);
                u64 tb = mul2(psiA[r], Xb.x);
                ta = fma2(psiB[r], Xa.y, ta);
                tb = fma2(psiB[r], Xb.y, tb);
                float2 fa = unpack2(ta);
                float2 fb = unpack2(tb);
                float ea = ex2(fa.x + fa.y);
                float eb = ex2(fb.x + fb.y);
                u64 eea = dup2(ea);
                u64 eeb = dup2(eb);
                sum[r] += ea;
                accA[r] = fma2(eea, Xa.x, accA[r]);
                accB[r] = fma2(eea, Xa.y, accB[r]);
                sum[r] += eb;
                accA[r] = fma2(eeb, Xb.x, accA[r]);
                accB[r] = fma2(eeb, Xb.y, accB[r]);
            }
        }
    }
    // --- Tail row ki = 10 ---
    {
        const ulonglong2* row = &xsh[base + 10 * SST];
        ulonglong2 xw[4];
        xw[0] = row[0]; xw[1] = row[1]; xw[2] = row[2];
        #pragma unroll
        for (int kj = 0; kj < FS; kj++) {
            if (kj < 9) xw[(kj + 3) & 3] = row[kj + 3];
            #pragma unroll
            for (int r = 0; r < R; r++) {
                ulonglong2 X = xw[(kj + r) & 3];
                u64 t = mul2(psiA[r], X.x);
                t = fma2(psiB[r], X.y, t);
                float2 f = unpack2(t);
                float e = ex2(f.x + f.y);
                u64 ee = dup2(e);
                sum[r] += e;
                accA[r] = fma2(ee, X.x, accA[r]);
                accB[r] = fma2(ee, X.y, accB[r]);
            }
        }
    }

    // --- Epilogue: normalize, apply M, residual; float2 stores ---
    float a0[R], a1[R], a2[R], a3[R];
    #pragma unroll
    for (int r = 0; r < R; r++) {
        float inv = __frcp_rn(sum[r]);
        float2 fA = unpack2(accA[r]);
        float2 fB = unpack2(accB[r]);
        a0[r] = fA.x * inv;
        a1[r] = fA.y * inv;
        a2[r] = fB.x * inv;
        a3[r] = fB.y * inv;
    }
    float* ob = out + b * (C * HW);
    #pragma unroll
    for (int c = 0; c < C; c++) {
        float2 res;
        res.x = fmaf(wM[c*4+0], a0[0], fmaf(wM[c*4+1], a1[0], fmaf(wM[c*4+2], a2[0], wM[c*4+3] * a3[0]))) + xs[c][0];
        res.y = fmaf(wM[c*4+0], a0[1], fmaf(wM[c*4+1], a1[1], fmaf(wM[c*4+2], a2[1], wM[c*4+3] * a3[1]))) + xs[c][1];
        *(float2*)(ob + c * HW + pixbase) = res;
    }
}

// ---------------------------------------------------------------------------
extern "C" void kernel_launch(void* const* d_in, const int* in_sizes, int n_in,
                              void* d_out, int out_size)
{
    const float* x  = (const float*)d_in[0];
    const float* Wt = (const float*)d_in[1];
    const float* Wp = (const float*)d_in[2];
    const float* Wg = (const float*)d_in[3];
    const float* Ww = (const float*)d_in[4];
    float* out = (float*)d_out;

    dim3 grid(W / BW, H / BH, B);
    fused_kernel<<<grid, NTHREADS>>>(x, Wt, Wp, Wg, Ww, out);
}